// round 14
// baseline (speedup 1.0000x reference)
#include <cuda_runtime.h>

typedef unsigned long long u64;
#define FULLMASK 0xffffffffu

// ---- f32x2 packed helpers (sm_103a) ------------------------------------
__device__ __forceinline__ u64 pk(float lo, float hi){
    u64 r; asm("mov.b64 %0, {%1, %2};" : "=l"(r) : "f"(lo), "f"(hi)); return r;
}
__device__ __forceinline__ void unpk(u64 v, float &lo, float &hi){
    asm("mov.b64 {%0, %1}, %2;" : "=f"(lo), "=f"(hi) : "l"(v));
}
__device__ __forceinline__ u64 f2mul(u64 a, u64 b){
    u64 d; asm("mul.rn.f32x2 %0, %1, %2;" : "=l"(d) : "l"(a), "l"(b)); return d;
}
__device__ __forceinline__ u64 f2fma(u64 a, u64 b, u64 c){
    u64 d; asm("fma.rn.f32x2 %0, %1, %2, %3;" : "=l"(d) : "l"(a), "l"(b), "l"(c)); return d;
}
__device__ __forceinline__ u64 shflx64(u64 v, int m){
    float a, b; unpk(v, a, b);
    a = __shfl_xor_sync(FULLMASK, a, m);
    b = __shfl_xor_sync(FULLMASK, b, m);
    return pk(a, b);
}
__device__ __forceinline__ u64 swap_slots(u64 v){
    float a, b; unpk(v, a, b); return pk(b, a);
}
__device__ __forceinline__ float2 cmul(float2 a, float2 b){
    return make_float2(a.x*b.x - a.y*b.y, a.x*b.y + a.y*b.x);
}

// Splat table layout (row-contiguous, 12 u64 per gate):
//   row0 (lo):  [0..2] = g00 splats (x, -y, +y),  [3..5] = g01 splats
//   row1 (hi):  [6..8] = g11 splats,              [9..11] = g10 splats
// bfly coefficient fetch for a lane is just gp + 6*hi, roles [diag|off].

// Packed 2x2 complex gate on pair ((X0,Y0),(X1,Y1)) using the row-contiguous layout.
__device__ __forceinline__ void gap2(const u64* g, u64 &X0, u64 &Y0, u64 &X1, u64 &Y1){
    u64 nX0 = f2mul(g[0], X0); nX0 = f2fma(g[1],  Y0, nX0); nX0 = f2fma(g[3], X1, nX0); nX0 = f2fma(g[4],  Y1, nX0);
    u64 nY0 = f2mul(g[0], Y0); nY0 = f2fma(g[2],  X0, nY0); nY0 = f2fma(g[3], Y1, nY0); nY0 = f2fma(g[5],  X1, nY0);
    u64 nX1 = f2mul(g[9], X0); nX1 = f2fma(g[10], Y0, nX1); nX1 = f2fma(g[6], X1, nX1); nX1 = f2fma(g[7],  Y1, nX1);
    u64 nY1 = f2mul(g[9], Y0); nY1 = f2fma(g[11], X0, nY1); nY1 = f2fma(g[6], Y1, nY1); nY1 = f2fma(g[8],  X1, nY1);
    X0 = nX0; Y0 = nY0; X1 = nX1; Y1 = nY1;
}

// Shuffle butterfly on lane-xor 'mask'; 'hi' selects gate row (true bit / parity).
__device__ __forceinline__ void bfly(const u64* gp, int mask, bool hi, u64* X, u64* Y){
    const u64* gr = gp + (hi ? 6 : 0);
    u64 ax = gr[0], ayn = gr[1], ayp = gr[2];
    u64 bx = gr[3], byn = gr[4], byp = gr[5];
    #pragma unroll
    for (int p = 0; p < 8; p++){
        u64 OX = shflx64(X[p], mask);
        u64 OY = shflx64(Y[p], mask);
        u64 nX = f2mul(ax, X[p]); nX = f2fma(ayn, Y[p], nX);
        nX = f2fma(bx, OX, nX);   nX = f2fma(byn, OY, nX);
        u64 nY = f2mul(ax, Y[p]); nY = f2fma(ayp, X[p], nY);
        nY = f2fma(bx, OY, nY);   nY = f2fma(byp, OX, nY);
        X[p] = nX; Y[p] = nY;
    }
}

// Butterfly on combined mask (lane bit0 XOR p bit2): partner at (lane^1, p^4).
__device__ __forceinline__ void bfly_lp(const u64* gp, bool hi, u64* X, u64* Y){
    const u64* gr = gp + (hi ? 6 : 0);
    u64 ax = gr[0], ayn = gr[1], ayp = gr[2];
    u64 bx = gr[3], byn = gr[4], byp = gr[5];
    #pragma unroll
    for (int p = 0; p < 4; p++){
        u64 OXa = shflx64(X[p+4], 1), OYa = shflx64(Y[p+4], 1);
        u64 OXb = shflx64(X[p],   1), OYb = shflx64(Y[p],   1);
        u64 nX0 = f2mul(ax, X[p]);   nX0 = f2fma(ayn, Y[p],   nX0); nX0 = f2fma(bx, OXa, nX0); nX0 = f2fma(byn, OYa, nX0);
        u64 nY0 = f2mul(ax, Y[p]);   nY0 = f2fma(ayp, X[p],   nY0); nY0 = f2fma(bx, OYa, nY0); nY0 = f2fma(byp, OXa, nY0);
        u64 nX1 = f2mul(ax, X[p+4]); nX1 = f2fma(ayn, Y[p+4], nX1); nX1 = f2fma(bx, OXb, nX1); nX1 = f2fma(byn, OYb, nX1);
        u64 nY1 = f2mul(ax, Y[p+4]); nY1 = f2fma(ayp, X[p+4], nY1); nY1 = f2fma(bx, OYb, nY1); nY1 = f2fma(byp, OXb, nY1);
        X[p] = nX0; Y[p] = nY0; X[p+4] = nX1; Y[p+4] = nY1;
    }
}

// One CTA per sample.  4096 amps = 256 threads x 8 f32x2-packed complex pairs.
// Layout A: warp b2..b0 = wires 0,1,2; lane b4..b0 = wires 3..7; p b2..b0 = wires 8,9,10; slot = wire11.
// Layout B: warp b2..b0 = wires 5,6,7; lane b4..b0 = wires 0..4;  p/slot unchanged.
// CNOT chain sigma (prefix-xor) is bit-linear: warp-wire gates are pulled forward
// through sigma as 2-bit-mask butterflies; each cross-warp exchange is a PURE
// permutation (8 STS.128 + 8 LDS.128).
// The initial state (post RX encoding) is a PRODUCT state, so the ENTIRE layer 1
// (all 12 single-qubit gates) folds into per-wire init vectors v_w = G1_w(c,-is).
// sigma_3 folds into the readout coefficients -> only 2 exchanges total.
// (256,4): cap regs at 64 for 4 CTAs/SM -> 32 resident warps (occ ~49%).
__global__ void __launch_bounds__(256, 4) qsim_kernel(
    const float* __restrict__ x,        // [B,12]
    const float* __restrict__ params,   // [3,12,3]
    const float* __restrict__ hw,       // [12]
    const float* __restrict__ hb,       // [1]
    float* __restrict__ out)            // [B]
{
    __shared__ ulonglong2 ex[2048];     // 32KB exchange buffer
    __shared__ float2 sG[3][12][4];     // fused RY*RZ*RY scalar gates
    __shared__ u64 sGp[3][12][12];      // splat variants (row-contiguous layout)
    __shared__ float2 sV[12][2];        // layer-1-folded init vectors per wire
    __shared__ float sC[12], sS[12], sHw[12], sRed[8];

    const int tid  = threadIdx.x;
    const int lane = tid & 31;
    const int warp = tid >> 5;
    const int b    = blockIdx.x;

    // ---- Stage 0: fused gates + per-sample RX angles
    if (tid < 36){
        int l = tid / 12, i = tid % 12;
        float pa = params[(l*12 + i)*3 + 0];
        float pb = params[(l*12 + i)*3 + 1];
        float pc = params[(l*12 + i)*3 + 2];
        float ca, sa, cb, sb, cc, sc;
        sincosf(0.5f*pa, &sa, &ca);
        sincosf(0.5f*pb, &sb, &cb);
        sincosf(0.5f*pc, &sc, &cc);
        float2 em = make_float2(cb, -sb);
        float2 ep = make_float2(cb,  sb);
        float ccca = cc*ca, scsa = sc*sa, ccsa = cc*sa, scca = sc*ca;
        sG[l][i][0] = make_float2( ccca*em.x - scsa*ep.x,  ccca*em.y - scsa*ep.y);
        sG[l][i][1] = make_float2(-ccsa*em.x - scca*ep.x, -ccsa*em.y - scca*ep.y);
        sG[l][i][2] = make_float2( scca*em.x + ccsa*ep.x,  scca*em.y + ccsa*ep.y);
        sG[l][i][3] = make_float2(-scsa*em.x + ccca*ep.x, -scsa*em.y + ccca*ep.y);
    } else if (tid >= 64 && tid < 76){
        int i = tid - 64;
        float s, c;
        sincosf(0.5f * x[b*12 + i], &s, &c);
        sC[i] = c; sS[i] = s;
        sHw[i] = hw[i];
    }
    __syncthreads();

    // splats for per-wire gates (row-contiguous: e=0(g00)->0, 1(g01)->3, 3(g11)->6, 2(g10)->9)
    if (tid < 144){
        int l = tid / 48, r = tid % 48, i = r >> 2, e = r & 3;
        float2 g = sG[l][i][e];
        int base = 3 * (e ^ (e >> 1));
        sGp[l][i][base+0] = pk( g.x,  g.x);
        sGp[l][i][base+1] = pk(-g.y, -g.y);
        sGp[l][i][base+2] = pk( g.y,  g.y);
    } else if (tid >= 192 && tid < 204){
        // sV[w] = G1_w * (cos, -i sin): ENTIRE layer 1 folded into product init
        int w = tid - 192;
        float c = sC[w], s = sS[w];
        float2 g00 = sG[0][w][0], g01 = sG[0][w][1];
        float2 g10 = sG[0][w][2], g11 = sG[0][w][3];
        sV[w][0] = make_float2(g00.x*c + g01.y*s, g00.y*c - g01.x*s);
        sV[w][1] = make_float2(g10.x*c + g11.y*s, g10.y*c - g11.x*s);
    }
    __syncthreads();

    // ---- Init: product state = (RX encoding) followed by all layer-1 gates
    u64 X[8], Y[8];
    {
        float2 base = sV[0][(tid >> 7) & 1];
        #pragma unroll
        for (int i = 1; i < 8; i++)
            base = cmul(base, sV[i][(tid >> (7 - i)) & 1]);
        float2 t9[2], t10[4], t11[8];
        t9[0] = cmul(base, sV[8][0]);
        t9[1] = cmul(base, sV[8][1]);
        #pragma unroll
        for (int u = 0; u < 2; u++){
            t10[2*u]   = cmul(t9[u], sV[9][0]);
            t10[2*u+1] = cmul(t9[u], sV[9][1]);
        }
        #pragma unroll
        for (int u = 0; u < 4; u++){
            t11[2*u]   = cmul(t10[u], sV[10][0]);
            t11[2*u+1] = cmul(t10[u], sV[10][1]);
        }
        float2 v0 = sV[11][0], v1 = sV[11][1];
        #pragma unroll
        for (int p = 0; p < 8; p++){
            float2 a0 = cmul(t11[p], v0);
            float2 a1 = cmul(t11[p], v1);
            X[p] = pk(a0.x, a1.x);
            Y[p] = pk(a0.y, a1.y);
        }
    }

    // Local-gate helper (wires 8,9,10 on p bits + wire 11 on slot), layer l
    auto local_gates = [&](int l){
        {
            const u64* g = sGp[l][8];
            #pragma unroll
            for (int p = 0; p < 4; p++) gap2(g, X[p], Y[p], X[p+4], Y[p+4]);
        }
        {
            const u64* g = sGp[l][9];
            gap2(g, X[0], Y[0], X[2], Y[2]); gap2(g, X[1], Y[1], X[3], Y[3]);
            gap2(g, X[4], Y[4], X[6], Y[6]); gap2(g, X[5], Y[5], X[7], Y[7]);
        }
        {
            const u64* g = sGp[l][10];
            gap2(g, X[0], Y[0], X[1], Y[1]); gap2(g, X[2], Y[2], X[3], Y[3]);
            gap2(g, X[4], Y[4], X[5], Y[5]); gap2(g, X[6], Y[6], X[7], Y[7]);
        }
        float2 g00 = sG[l][11][0], g01 = sG[l][11][1];
        float2 g10 = sG[l][11][2], g11 = sG[l][11][3];
        #pragma unroll
        for (int p = 0; p < 8; p++){
            float x0, x1, y0, y1;
            unpk(X[p], x0, x1); unpk(Y[p], y0, y1);
            float nx0 = fmaf(g00.x, x0, fmaf(-g00.y, y0, fmaf(g01.x, x1, -g01.y*y1)));
            float ny0 = fmaf(g00.x, y0, fmaf( g00.y, x0, fmaf(g01.x, y1,  g01.y*x1)));
            float nx1 = fmaf(g10.x, x0, fmaf(-g10.y, y0, fmaf(g11.x, x1, -g11.y*y1)));
            float ny1 = fmaf(g10.x, y0, fmaf( g10.y, x0, fmaf(g11.x, y1,  g11.y*x1)));
            X[p] = pk(nx0, nx1); Y[p] = pk(ny0, ny1);
        }
    };

    // ======== Phase 1 (layout A): only pulled layer-2 gates on wires 5,6,7 ========
    // (layer-1 gates all folded into init; sigma-conjugated masks e_w^e_{w+1})
    {
        bool P5 = __popc(tid & 0xFC) & 1;   // parity wires 0..5
        bool P6 = __popc(tid & 0xFE) & 1;   // parity wires 0..6
        bool P7 = __popc(tid & 0xFF) & 1;   // parity wires 0..7
        bfly(sGp[1][5], 6, P5, X, Y);       // wires 5^6 (lane b2^b1)
        bfly(sGp[1][6], 3, P6, X, Y);       // wires 6^7 (lane b1^b0)
        bfly_lp(sGp[1][7], P7, X, Y);       // wires 7^8 (lane b0 ^ p b2)
    }

    // ---- Exchange X1: sigma + relayout A->B (pure permutation) ----
    __syncthreads();
    {
        int s0=(warp>>2)&1, s1=(warp>>1)&1, s2=warp&1;
        int s3=(lane>>4)&1, s4=(lane>>3)&1, s5=(lane>>2)&1, s6=(lane>>1)&1, s7=lane&1;
        int mb = (s2^s6) | ((s3^s7)<<1) | (s5<<2) | (s0<<3)|(s1<<4)|(s4<<5)|(s6<<6)|(s7<<7);
        #pragma unroll
        for (int p = 0; p < 8; p++){
            int addr = mb | (((p>>2)&1)<<8) | (((p>>1)&1)<<9) | ((p&1)<<10);
            ex[addr] = make_ulonglong2(X[p], Y[p]);
        }
    }
    __syncthreads();
    {
        int d0=(lane>>4)&1, d1=(lane>>3)&1, d2=(lane>>2)&1, d3=(lane>>1)&1, d4=lane&1;
        int d5=(warp>>2)&1, d6=(warp>>1)&1, d7=warp&1;
        int s0=d0, s1=d0^d1, s2=d1^d2, s3=d2^d3, s4=d3^d4, s5=d4^d5, s6=d5^d6, s7=d6^d7;
        int gb = (s2^s6) | ((s3^s7)<<1) | (s5<<2) | (s0<<3)|(s1<<4)|(s4<<5)|(s6<<6)|(s7<<7);
        #pragma unroll
        for (int p = 0; p < 8; p++){
            int d8=(p>>2)&1, d9=(p>>1)&1, d10=p&1;
            int s8=d7^d8, s9=d8^d9, s10=d9^d10;
            ulonglong2 v = ex[gb | (s8<<8)|(s9<<9)|(s10<<10)];
            if (p & 1){ X[p] = swap_slots(v.x); Y[p] = swap_slots(v.y); }
            else      { X[p] = v.x;            Y[p] = v.y; }
        }
    }

    // ======== Phase 2 (layout B): layer-2 gates on wires 0-4, 8-11 ========
    local_gates(1);
    bfly(sGp[1][0], 16, (lane>>4)&1, X, Y);
    bfly(sGp[1][1],  8, (lane>>3)&1, X, Y);
    bfly(sGp[1][2],  4, (lane>>2)&1, X, Y);
    bfly(sGp[1][3],  2, (lane>>1)&1, X, Y);
    bfly(sGp[1][4],  1,  lane&1,     X, Y);
    // Pulled layer-3 gates on wires 0,1,2 (masks e_w^e_{w+1}, all lane bits in B)
    {
        bool P0 = (lane>>4)&1;
        bool P1 = __popc(lane & 24) & 1;
        bool P2 = __popc(lane & 28) & 1;
        bfly(sGp[2][0], 24, P0, X, Y);      // wires 0^1 (lane b4^b3)
        bfly(sGp[2][1], 12, P1, X, Y);      // wires 1^2 (lane b3^b2)
        bfly(sGp[2][2],  6, P2, X, Y);      // wires 2^3 (lane b2^b1)
    }

    // ---- Exchange X2: sigma + relayout B->A (pure permutation) ----
    __syncthreads();
    {
        int s0=(lane>>4)&1, s1=(lane>>3)&1, s2=(lane>>2)&1, s3=(lane>>1)&1, s4=lane&1;
        int s5=(warp>>2)&1, s6=(warp>>1)&1, s7=warp&1;
        int mb = (s5^s3) | ((s7^s4)<<1) | (s0<<3)|(s1<<4)|(s2<<5)|(s3<<6)|(s4<<7)|(s6<<8);
        #pragma unroll
        for (int p = 0; p < 8; p++){
            int s8=(p>>2)&1, s9=(p>>1)&1, s10=p&1;
            ex[mb | ((s8^s2)<<2) | (s9<<9)|(s10<<10)] = make_ulonglong2(X[p], Y[p]);
        }
    }
    __syncthreads();
    {
        int d0=(warp>>2)&1, d1=(warp>>1)&1, d2=warp&1;
        int d3=(lane>>4)&1, d4=(lane>>3)&1, d5=(lane>>2)&1, d6=(lane>>1)&1, d7=lane&1;
        int s0=d0, s1=d0^d1, s2=d1^d2, s3=d2^d3, s4=d3^d4, s5=d4^d5, s6=d5^d6, s7=d6^d7;
        int gb = (s5^s3) | ((s7^s4)<<1) | (s0<<3)|(s1<<4)|(s2<<5)|(s3<<6)|(s4<<7)|(s6<<8);
        #pragma unroll
        for (int p = 0; p < 8; p++){
            int d8=(p>>2)&1, d9=(p>>1)&1, d10=p&1;
            int s8=d7^d8, s9=d8^d9, s10=d9^d10;
            ulonglong2 v = ex[gb | ((s8^s2)<<2) | (s9<<9)|(s10<<10)];
            if (p & 1){ X[p] = swap_slots(v.x); Y[p] = swap_slots(v.y); }
            else      { X[p] = v.x;            Y[p] = v.y; }
        }
    }

    // ======== Phase 3 (layout A): layer-3 gates on wires 3-11 ========
    local_gates(2);
    bfly(sGp[2][3], 16, (lane>>4)&1, X, Y);
    bfly(sGp[2][4],  8, (lane>>3)&1, X, Y);
    bfly(sGp[2][5],  4, (lane>>2)&1, X, Y);
    bfly(sGp[2][6],  2, (lane>>1)&1, X, Y);
    bfly(sGp[2][7],  1,  lane&1,     X, Y);

    // ---- Readout: sigma_3 folded via prefix parities.
    int P = 0; float basec = 0.f;
    #pragma unroll
    for (int i = 0; i < 8; i++){
        P ^= (tid >> (7 - i)) & 1;
        basec += P ? -sHw[i] : sHw[i];
    }
    float h8 = sHw[8], h9 = sHw[9], h10 = sHw[10], h11 = sHw[11];
    u64 acc = pk(0.f, 0.f);
    #pragma unroll
    for (int p = 0; p < 8; p++){
        int P8  = P  ^ ((p>>2)&1);
        int P9  = P8 ^ ((p>>1)&1);
        int P10 = P9 ^ (p&1);
        float cp = basec + (P8 ? -h8 : h8) + (P9 ? -h9 : h9) + (P10 ? -h10 : h10);
        float t11 = P10 ? -h11 : h11;
        u64 cpair = pk(cp + t11, cp - t11);
        u64 r2 = f2mul(X[p], X[p]);
        r2 = f2fma(Y[p], Y[p], r2);
        acc = f2fma(cpair, r2, acc);
    }
    float plo, phi; unpk(acc, plo, phi);
    float partial = plo + phi;
    #pragma unroll
    for (int off = 16; off; off >>= 1)
        partial += __shfl_down_sync(FULLMASK, partial, off);
    if (lane == 0) sRed[warp] = partial;
    __syncthreads();
    if (tid == 0){
        float s = hb[0];
        #pragma unroll
        for (int w = 0; w < 8; w++) s += sRed[w];
        out[b] = s;
    }
}

extern "C" void kernel_launch(void* const* d_in, const int* in_sizes, int n_in,
                              void* d_out, int out_size)
{
    const float* x      = (const float*)d_in[0];
    const float* params = (const float*)d_in[1];
    const float* hw     = (const float*)d_in[2];
    const float* hb     = (const float*)d_in[3];
    float* out = (float*)d_out;
    (void)in_sizes; (void)n_in;
    qsim_kernel<<<out_size, 256>>>(x, params, hw, hb, out);
}

// round 15
// speedup vs baseline: 1.0946x; 1.0946x over previous
#include <cuda_runtime.h>

typedef unsigned long long u64;
#define FULLMASK 0xffffffffu

// ---- f32x2 packed helpers (sm_103a) ------------------------------------
__device__ __forceinline__ u64 pk(float lo, float hi){
    u64 r; asm("mov.b64 %0, {%1, %2};" : "=l"(r) : "f"(lo), "f"(hi)); return r;
}
__device__ __forceinline__ void unpk(u64 v, float &lo, float &hi){
    asm("mov.b64 {%0, %1}, %2;" : "=f"(lo), "=f"(hi) : "l"(v));
}
__device__ __forceinline__ u64 f2mul(u64 a, u64 b){
    u64 d; asm("mul.rn.f32x2 %0, %1, %2;" : "=l"(d) : "l"(a), "l"(b)); return d;
}
__device__ __forceinline__ u64 f2fma(u64 a, u64 b, u64 c){
    u64 d; asm("fma.rn.f32x2 %0, %1, %2, %3;" : "=l"(d) : "l"(a), "l"(b), "l"(c)); return d;
}
__device__ __forceinline__ u64 shflx64(u64 v, int m){
    float a, b; unpk(v, a, b);
    a = __shfl_xor_sync(FULLMASK, a, m);
    b = __shfl_xor_sync(FULLMASK, b, m);
    return pk(a, b);
}
__device__ __forceinline__ u64 swap_slots(u64 v){
    float a, b; unpk(v, a, b); return pk(b, a);
}
__device__ __forceinline__ float2 cmul(float2 a, float2 b){
    return make_float2(a.x*b.x - a.y*b.y, a.x*b.y + a.y*b.x);
}

// Splat table layout (row-contiguous, 12 u64 per gate):
//   row0 (lo):  [0..2] = g00 splats (x, -y, +y),  [3..5] = g01 splats
//   row1 (hi):  [6..8] = g11 splats,              [9..11] = g10 splats
// bfly coefficient fetch for a lane is just gp + 6*hi, roles [diag|off].

// Packed 2x2 complex gate on pair ((X0,Y0),(X1,Y1)) using the row-contiguous layout.
__device__ __forceinline__ void gap2(const u64* g, u64 &X0, u64 &Y0, u64 &X1, u64 &Y1){
    u64 nX0 = f2mul(g[0], X0); nX0 = f2fma(g[1],  Y0, nX0); nX0 = f2fma(g[3], X1, nX0); nX0 = f2fma(g[4],  Y1, nX0);
    u64 nY0 = f2mul(g[0], Y0); nY0 = f2fma(g[2],  X0, nY0); nY0 = f2fma(g[3], Y1, nY0); nY0 = f2fma(g[5],  X1, nY0);
    u64 nX1 = f2mul(g[9], X0); nX1 = f2fma(g[10], Y0, nX1); nX1 = f2fma(g[6], X1, nX1); nX1 = f2fma(g[7],  Y1, nX1);
    u64 nY1 = f2mul(g[9], Y0); nY1 = f2fma(g[11], X0, nY1); nY1 = f2fma(g[6], Y1, nY1); nY1 = f2fma(g[8],  X1, nY1);
    X0 = nX0; Y0 = nY0; X1 = nX1; Y1 = nY1;
}

// Shuffle butterfly on lane-xor 'mask'; 'hi' selects gate row (true bit / parity).
__device__ __forceinline__ void bfly(const u64* gp, int mask, bool hi, u64* X, u64* Y){
    const u64* gr = gp + (hi ? 6 : 0);
    u64 ax = gr[0], ayn = gr[1], ayp = gr[2];
    u64 bx = gr[3], byn = gr[4], byp = gr[5];
    #pragma unroll
    for (int p = 0; p < 8; p++){
        u64 OX = shflx64(X[p], mask);
        u64 OY = shflx64(Y[p], mask);
        u64 nX = f2mul(ax, X[p]); nX = f2fma(ayn, Y[p], nX);
        nX = f2fma(bx, OX, nX);   nX = f2fma(byn, OY, nX);
        u64 nY = f2mul(ax, Y[p]); nY = f2fma(ayp, X[p], nY);
        nY = f2fma(bx, OY, nY);   nY = f2fma(byp, OX, nY);
        X[p] = nX; Y[p] = nY;
    }
}

// Butterfly on combined mask (lane bit0 XOR p bit2): partner at (lane^1, p^4).
__device__ __forceinline__ void bfly_lp(const u64* gp, bool hi, u64* X, u64* Y){
    const u64* gr = gp + (hi ? 6 : 0);
    u64 ax = gr[0], ayn = gr[1], ayp = gr[2];
    u64 bx = gr[3], byn = gr[4], byp = gr[5];
    #pragma unroll
    for (int p = 0; p < 4; p++){
        u64 OXa = shflx64(X[p+4], 1), OYa = shflx64(Y[p+4], 1);
        u64 OXb = shflx64(X[p],   1), OYb = shflx64(Y[p],   1);
        u64 nX0 = f2mul(ax, X[p]);   nX0 = f2fma(ayn, Y[p],   nX0); nX0 = f2fma(bx, OXa, nX0); nX0 = f2fma(byn, OYa, nX0);
        u64 nY0 = f2mul(ax, Y[p]);   nY0 = f2fma(ayp, X[p],   nY0); nY0 = f2fma(bx, OYa, nY0); nY0 = f2fma(byp, OXa, nY0);
        u64 nX1 = f2mul(ax, X[p+4]); nX1 = f2fma(ayn, Y[p+4], nX1); nX1 = f2fma(bx, OXb, nX1); nX1 = f2fma(byn, OYb, nX1);
        u64 nY1 = f2mul(ax, Y[p+4]); nY1 = f2fma(ayp, X[p+4], nY1); nY1 = f2fma(bx, OYb, nY1); nY1 = f2fma(byp, OXb, nY1);
        X[p] = nX0; Y[p] = nY0; X[p+4] = nX1; Y[p+4] = nY1;
    }
}

// One CTA per sample.  4096 amps = 256 threads x 8 f32x2-packed complex pairs.
// Layout A: warp b2..b0 = wires 0,1,2; lane b4..b0 = wires 3..7; p b2..b0 = wires 8,9,10; slot = wire11.
// Layout B: warp b2..b0 = wires 5,6,7; lane b4..b0 = wires 0..4;  p/slot unchanged.
// CNOT chain sigma (prefix-xor) is bit-linear: warp-wire gates are pulled forward
// through sigma as 2-bit-mask butterflies; each cross-warp exchange is a PURE
// permutation (8 STS.128 + 8 LDS.128).
// The initial state (post RX encoding) is a PRODUCT state, so the ENTIRE layer 1
// (all 12 single-qubit gates) folds into per-wire init vectors v_w = G1_w(c,-is).
// sigma_3 folds into the readout coefficients -> only 2 exchanges total.
// Slot-wire (11) gates use packed broadcast form: nX = C1*xx0+C2*xx1+C3*yy0+C4*yy1
// (shifts 128 scalar FFMA/thread off the fma pipe into FFMA2+MOV).
__global__ void __launch_bounds__(256, 3) qsim_kernel(
    const float* __restrict__ x,        // [B,12]
    const float* __restrict__ params,   // [3,12,3]
    const float* __restrict__ hw,       // [12]
    const float* __restrict__ hb,       // [1]
    float* __restrict__ out)            // [B]
{
    __shared__ ulonglong2 ex[2048];     // 32KB exchange buffer
    __shared__ float2 sG[3][12][4];     // fused RY*RZ*RY scalar gates
    __shared__ u64 sGp[3][12][12];      // splat variants (row-contiguous layout)
    __shared__ u64 sGs[2][6];           // slot-gate column-pair splats, layers 2,3
    __shared__ float2 sV[12][2];        // layer-1-folded init vectors per wire
    __shared__ float sC[12], sS[12], sHw[12], sRed[8];

    const int tid  = threadIdx.x;
    const int lane = tid & 31;
    const int warp = tid >> 5;
    const int b    = blockIdx.x;

    // ---- Stage 0: fused gates + per-sample RX angles
    if (tid < 36){
        int l = tid / 12, i = tid % 12;
        float pa = params[(l*12 + i)*3 + 0];
        float pb = params[(l*12 + i)*3 + 1];
        float pc = params[(l*12 + i)*3 + 2];
        float ca, sa, cb, sb, cc, sc;
        sincosf(0.5f*pa, &sa, &ca);
        sincosf(0.5f*pb, &sb, &cb);
        sincosf(0.5f*pc, &sc, &cc);
        float2 em = make_float2(cb, -sb);
        float2 ep = make_float2(cb,  sb);
        float ccca = cc*ca, scsa = sc*sa, ccsa = cc*sa, scca = sc*ca;
        sG[l][i][0] = make_float2( ccca*em.x - scsa*ep.x,  ccca*em.y - scsa*ep.y);
        sG[l][i][1] = make_float2(-ccsa*em.x - scca*ep.x, -ccsa*em.y - scca*ep.y);
        sG[l][i][2] = make_float2( scca*em.x + ccsa*ep.x,  scca*em.y + ccsa*ep.y);
        sG[l][i][3] = make_float2(-scsa*em.x + ccca*ep.x, -scsa*em.y + ccca*ep.y);
    } else if (tid >= 64 && tid < 76){
        int i = tid - 64;
        float s, c;
        sincosf(0.5f * x[b*12 + i], &s, &c);
        sC[i] = c; sS[i] = s;
        sHw[i] = hw[i];
    }
    __syncthreads();

    // splats for per-wire gates (row-contiguous: e=0(g00)->0, 1(g01)->3, 3(g11)->6, 2(g10)->9)
    if (tid < 144){
        int l = tid / 48, r = tid % 48, i = r >> 2, e = r & 3;
        float2 g = sG[l][i][e];
        int base = 3 * (e ^ (e >> 1));
        sGp[l][i][base+0] = pk( g.x,  g.x);
        sGp[l][i][base+1] = pk(-g.y, -g.y);
        sGp[l][i][base+2] = pk( g.y,  g.y);
    } else if (tid >= 192 && tid < 204){
        // sV[w] = G1_w * (cos, -i sin): ENTIRE layer 1 folded into product init
        int w = tid - 192;
        float c = sC[w], s = sS[w];
        float2 g00 = sG[0][w][0], g01 = sG[0][w][1];
        float2 g10 = sG[0][w][2], g11 = sG[0][w][3];
        sV[w][0] = make_float2(g00.x*c + g01.y*s, g00.y*c - g01.x*s);
        sV[w][1] = make_float2(g10.x*c + g11.y*s, g10.y*c - g11.x*s);
    } else if (tid >= 204 && tid < 206){
        // slot-gate column-pair splats for wire 11, layers l=1,2
        int l = tid - 204;                // 0 -> layer index 1, 1 -> layer index 2
        float2 g00 = sG[l+1][11][0], g01 = sG[l+1][11][1];
        float2 g10 = sG[l+1][11][2], g11 = sG[l+1][11][3];
        sGs[l][0] = pk( g00.x,  g10.x);   // C1
        sGs[l][1] = pk( g01.x,  g11.x);   // C2
        sGs[l][2] = pk(-g00.y, -g10.y);   // C3
        sGs[l][3] = pk(-g01.y, -g11.y);   // C4
        sGs[l][4] = pk( g00.y,  g10.y);   // C5
        sGs[l][5] = pk( g01.y,  g11.y);   // C6
    }
    __syncthreads();

    // ---- Init: product state = (RX encoding) followed by all layer-1 gates
    u64 X[8], Y[8];
    {
        float2 base = sV[0][(tid >> 7) & 1];
        #pragma unroll
        for (int i = 1; i < 8; i++)
            base = cmul(base, sV[i][(tid >> (7 - i)) & 1]);
        float2 t9[2], t10[4];
        t9[0] = cmul(base, sV[8][0]);
        t9[1] = cmul(base, sV[8][1]);
        #pragma unroll
        for (int u = 0; u < 2; u++){
            t10[2*u]   = cmul(t9[u], sV[9][0]);
            t10[2*u+1] = cmul(t9[u], sV[9][1]);
        }
        float2 w0 = sV[10][0], w1 = sV[10][1];
        float2 v0 = sV[11][0], v1 = sV[11][1];
        #pragma unroll
        for (int u = 0; u < 4; u++){
            float2 tl = cmul(t10[u], w0);
            float2 th = cmul(t10[u], w1);
            float2 a0 = cmul(tl, v0);
            float2 a1 = cmul(tl, v1);
            X[2*u]   = pk(a0.x, a1.x);
            Y[2*u]   = pk(a0.y, a1.y);
            a0 = cmul(th, v0);
            a1 = cmul(th, v1);
            X[2*u+1] = pk(a0.x, a1.x);
            Y[2*u+1] = pk(a0.y, a1.y);
        }
    }

    // Local-gate helper (wires 8,9,10 on p bits + wire 11 on slot), layer l (1 or 2)
    auto local_gates = [&](int l){
        {
            const u64* g = sGp[l][8];
            #pragma unroll
            for (int p = 0; p < 4; p++) gap2(g, X[p], Y[p], X[p+4], Y[p+4]);
        }
        {
            const u64* g = sGp[l][9];
            gap2(g, X[0], Y[0], X[2], Y[2]); gap2(g, X[1], Y[1], X[3], Y[3]);
            gap2(g, X[4], Y[4], X[6], Y[6]); gap2(g, X[5], Y[5], X[7], Y[7]);
        }
        {
            const u64* g = sGp[l][10];
            gap2(g, X[0], Y[0], X[1], Y[1]); gap2(g, X[2], Y[2], X[3], Y[3]);
            gap2(g, X[4], Y[4], X[5], Y[5]); gap2(g, X[6], Y[6], X[7], Y[7]);
        }
        // Wire-11 slot gate, packed broadcast form
        {
            const u64* cs = sGs[l-1];
            u64 C1 = cs[0], C2 = cs[1], C3 = cs[2], C4 = cs[3], C5 = cs[4], C6 = cs[5];
            #pragma unroll
            for (int p = 0; p < 8; p++){
                float x0, x1, y0, y1;
                unpk(X[p], x0, x1); unpk(Y[p], y0, y1);
                u64 XX0 = pk(x0, x0), XX1 = pk(x1, x1);
                u64 YY0 = pk(y0, y0), YY1 = pk(y1, y1);
                u64 nX = f2mul(C1, XX0); nX = f2fma(C2, XX1, nX);
                nX = f2fma(C3, YY0, nX); nX = f2fma(C4, YY1, nX);
                u64 nY = f2mul(C5, XX0); nY = f2fma(C6, XX1, nY);
                nY = f2fma(C1, YY0, nY); nY = f2fma(C2, YY1, nY);
                X[p] = nX; Y[p] = nY;
            }
        }
    };

    // ======== Phase 1 (layout A): only pulled layer-2 gates on wires 5,6,7 ========
    // (layer-1 gates all folded into init; sigma-conjugated masks e_w^e_{w+1})
    {
        bool P5 = __popc(tid & 0xFC) & 1;   // parity wires 0..5
        bool P6 = __popc(tid & 0xFE) & 1;   // parity wires 0..6
        bool P7 = __popc(tid & 0xFF) & 1;   // parity wires 0..7
        bfly(sGp[1][5], 6, P5, X, Y);       // wires 5^6 (lane b2^b1)
        bfly(sGp[1][6], 3, P6, X, Y);       // wires 6^7 (lane b1^b0)
        bfly_lp(sGp[1][7], P7, X, Y);       // wires 7^8 (lane b0 ^ p b2)
    }

    // ---- Exchange X1: sigma + relayout A->B (pure permutation) ----
    __syncthreads();
    {
        int s0=(warp>>2)&1, s1=(warp>>1)&1, s2=warp&1;
        int s3=(lane>>4)&1, s4=(lane>>3)&1, s5=(lane>>2)&1, s6=(lane>>1)&1, s7=lane&1;
        int mb = (s2^s6) | ((s3^s7)<<1) | (s5<<2) | (s0<<3)|(s1<<4)|(s4<<5)|(s6<<6)|(s7<<7);
        #pragma unroll
        for (int p = 0; p < 8; p++){
            int addr = mb | (((p>>2)&1)<<8) | (((p>>1)&1)<<9) | ((p&1)<<10);
            ex[addr] = make_ulonglong2(X[p], Y[p]);
        }
    }
    __syncthreads();
    {
        int d0=(lane>>4)&1, d1=(lane>>3)&1, d2=(lane>>2)&1, d3=(lane>>1)&1, d4=lane&1;
        int d5=(warp>>2)&1, d6=(warp>>1)&1, d7=warp&1;
        int s0=d0, s1=d0^d1, s2=d1^d2, s3=d2^d3, s4=d3^d4, s5=d4^d5, s6=d5^d6, s7=d6^d7;
        int gb = (s2^s6) | ((s3^s7)<<1) | (s5<<2) | (s0<<3)|(s1<<4)|(s4<<5)|(s6<<6)|(s7<<7);
        #pragma unroll
        for (int p = 0; p < 8; p++){
            int d8=(p>>2)&1, d9=(p>>1)&1, d10=p&1;
            int s8=d7^d8, s9=d8^d9, s10=d9^d10;
            ulonglong2 v = ex[gb | (s8<<8)|(s9<<9)|(s10<<10)];
            if (p & 1){ X[p] = swap_slots(v.x); Y[p] = swap_slots(v.y); }
            else      { X[p] = v.x;            Y[p] = v.y; }
        }
    }

    // ======== Phase 2 (layout B): layer-2 gates on wires 0-4, 8-11 ========
    local_gates(1);
    bfly(sGp[1][0], 16, (lane>>4)&1, X, Y);
    bfly(sGp[1][1],  8, (lane>>3)&1, X, Y);
    bfly(sGp[1][2],  4, (lane>>2)&1, X, Y);
    bfly(sGp[1][3],  2, (lane>>1)&1, X, Y);
    bfly(sGp[1][4],  1,  lane&1,     X, Y);
    // Pulled layer-3 gates on wires 0,1,2 (masks e_w^e_{w+1}, all lane bits in B)
    {
        bool P0 = (lane>>4)&1;
        bool P1 = __popc(lane & 24) & 1;
        bool P2 = __popc(lane & 28) & 1;
        bfly(sGp[2][0], 24, P0, X, Y);      // wires 0^1 (lane b4^b3)
        bfly(sGp[2][1], 12, P1, X, Y);      // wires 1^2 (lane b3^b2)
        bfly(sGp[2][2],  6, P2, X, Y);      // wires 2^3 (lane b2^b1)
    }

    // ---- Exchange X2: sigma + relayout B->A (pure permutation) ----
    __syncthreads();
    {
        int s0=(lane>>4)&1, s1=(lane>>3)&1, s2=(lane>>2)&1, s3=(lane>>1)&1, s4=lane&1;
        int s5=(warp>>2)&1, s6=(warp>>1)&1, s7=warp&1;
        int mb = (s5^s3) | ((s7^s4)<<1) | (s0<<3)|(s1<<4)|(s2<<5)|(s3<<6)|(s4<<7)|(s6<<8);
        #pragma unroll
        for (int p = 0; p < 8; p++){
            int s8=(p>>2)&1, s9=(p>>1)&1, s10=p&1;
            ex[mb | ((s8^s2)<<2) | (s9<<9)|(s10<<10)] = make_ulonglong2(X[p], Y[p]);
        }
    }
    __syncthreads();
    {
        int d0=(warp>>2)&1, d1=(warp>>1)&1, d2=warp&1;
        int d3=(lane>>4)&1, d4=(lane>>3)&1, d5=(lane>>2)&1, d6=(lane>>1)&1, d7=lane&1;
        int s0=d0, s1=d0^d1, s2=d1^d2, s3=d2^d3, s4=d3^d4, s5=d4^d5, s6=d5^d6, s7=d6^d7;
        int gb = (s5^s3) | ((s7^s4)<<1) | (s0<<3)|(s1<<4)|(s2<<5)|(s3<<6)|(s4<<7)|(s6<<8);
        #pragma unroll
        for (int p = 0; p < 8; p++){
            int d8=(p>>2)&1, d9=(p>>1)&1, d10=p&1;
            int s8=d7^d8, s9=d8^d9, s10=d9^d10;
            ulonglong2 v = ex[gb | ((s8^s2)<<2) | (s9<<9)|(s10<<10)];
            if (p & 1){ X[p] = swap_slots(v.x); Y[p] = swap_slots(v.y); }
            else      { X[p] = v.x;            Y[p] = v.y; }
        }
    }

    // ======== Phase 3 (layout A): layer-3 gates on wires 3-11 ========
    local_gates(2);
    bfly(sGp[2][3], 16, (lane>>4)&1, X, Y);
    bfly(sGp[2][4],  8, (lane>>3)&1, X, Y);
    bfly(sGp[2][5],  4, (lane>>2)&1, X, Y);
    bfly(sGp[2][6],  2, (lane>>1)&1, X, Y);
    bfly(sGp[2][7],  1,  lane&1,     X, Y);

    // ---- Readout: sigma_3 folded via prefix parities.
    int P = 0; float basec = 0.f;
    #pragma unroll
    for (int i = 0; i < 8; i++){
        P ^= (tid >> (7 - i)) & 1;
        basec += P ? -sHw[i] : sHw[i];
    }
    float h8 = sHw[8], h9 = sHw[9], h10 = sHw[10], h11 = sHw[11];
    u64 acc = pk(0.f, 0.f);
    #pragma unroll
    for (int p = 0; p < 8; p++){
        int P8  = P  ^ ((p>>2)&1);
        int P9  = P8 ^ ((p>>1)&1);
        int P10 = P9 ^ (p&1);
        float cp = basec + (P8 ? -h8 : h8) + (P9 ? -h9 : h9) + (P10 ? -h10 : h10);
        float t11 = P10 ? -h11 : h11;
        u64 cpair = pk(cp + t11, cp - t11);
        u64 r2 = f2mul(X[p], X[p]);
        r2 = f2fma(Y[p], Y[p], r2);
        acc = f2fma(cpair, r2, acc);
    }
    float plo, phi; unpk(acc, plo, phi);
    float partial = plo + phi;
    #pragma unroll
    for (int off = 16; off; off >>= 1)
        partial += __shfl_down_sync(FULLMASK, partial, off);
    if (lane == 0) sRed[warp] = partial;
    __syncthreads();
    if (tid == 0){
        float s = hb[0];
        #pragma unroll
        for (int w = 0; w < 8; w++) s += sRed[w];
        out[b] = s;
    }
}

extern "C" void kernel_launch(void* const* d_in, const int* in_sizes, int n_in,
                              void* d_out, int out_size)
{
    const float* x      = (const float*)d_in[0];
    const float* params = (const float*)d_in[1];
    const float* hw     = (const float*)d_in[2];
    const float* hb     = (const float*)d_in[3];
    float* out = (float*)d_out;
    (void)in_sizes; (void)n_in;
    qsim_kernel<<<out_size, 256>>>(x, params, hw, hb, out);
}